// round 1
// baseline (speedup 1.0000x reference)
#include <cuda_runtime.h>
#include <math.h>

#define HIDDEN 512
#define BATCH  8
#define HW     2304   // 48*48

// ---------------- scratch (static device globals; no allocs allowed) ----------
static __device__ float g_q  [(size_t)BATCH * HIDDEN * HW];
static __device__ float g_k  [(size_t)BATCH * HIDDEN * HW];
static __device__ float g_v  [(size_t)BATCH * HIDDEN * HW];
static __device__ float g_ctx[(size_t)BATCH * HIDDEN * HW];
static __device__ float g_s  [(size_t)BATCH * HW * HW];

// ---------------- generic batched tiled GEMM --------------------------------
// C[m][n] = alpha * sum_k opA(m,k) * opB(k,n) + bias[m]
//   TA=0: A is [M,K] row-major (lda = row stride)   TA=1: A is [K,M]
//   TB=0: B is [K,N] row-major                      TB=1: B is [N,K]
// All of M,N divisible by 128 and K divisible by 16 (true for every call here).
constexpr int BM = 128, BN = 128, BK = 16, TM = 8, TN = 8;
constexpr int PAD = 4;

template<bool TA, bool TB>
__global__ __launch_bounds__(256, 2)
void gemm_kernel(const float* __restrict__ A, const float* __restrict__ B,
                 float* __restrict__ C, const float* __restrict__ bias,
                 int M, int N, int K, int lda, int ldb, int ldc,
                 long long sA, long long sB, long long sC, float alpha)
{
    __shared__ float As[BK][BM + PAD];
    __shared__ float Bs[BK][BN + PAD];

    const int bz = blockIdx.z;
    A += (long long)bz * sA;
    B += (long long)bz * sB;
    C += (long long)bz * sC;

    const int bm = blockIdx.y * BM;
    const int bn = blockIdx.x * BN;
    const int tid = threadIdx.x;       // 256 threads
    const int tx = tid & 15;           // n direction
    const int ty = tid >> 4;           // m direction

    float acc[TM][TN];
#pragma unroll
    for (int i = 0; i < TM; i++)
#pragma unroll
        for (int j = 0; j < TN; j++) acc[i][j] = 0.f;

    for (int k0 = 0; k0 < K; k0 += BK) {
        // ---- load A tile into As[k][m] ----
        if (TA) {
            // A[K,M]: rows k (16), contiguous in m (128)
#pragma unroll
            for (int t = 0; t < 2; t++) {
                int fi = tid + t * 256;          // 512 float4s
                int kl = fi >> 5;                // 0..15
                int m4 = (fi & 31) << 2;         // 0..124
                float4 vv = *(const float4*)&A[(long long)(k0 + kl) * lda + bm + m4];
                *(float4*)&As[kl][m4] = vv;
            }
        } else {
            // A[M,K]: rows m (128), contiguous in k (16) -> transpose into smem
#pragma unroll
            for (int t = 0; t < 2; t++) {
                int fi = tid + t * 256;
                int ml = fi >> 2;                // 0..127
                int k4 = (fi & 3) << 2;          // 0,4,8,12
                float4 vv = *(const float4*)&A[(long long)(bm + ml) * lda + k0 + k4];
                As[k4 + 0][ml] = vv.x;
                As[k4 + 1][ml] = vv.y;
                As[k4 + 2][ml] = vv.z;
                As[k4 + 3][ml] = vv.w;
            }
        }
        // ---- load B tile into Bs[k][n] ----
        if (TB) {
            // B[N,K]: rows n (128), contiguous in k (16) -> transpose into smem
#pragma unroll
            for (int t = 0; t < 2; t++) {
                int fi = tid + t * 256;
                int nl = fi >> 2;
                int k4 = (fi & 3) << 2;
                float4 vv = *(const float4*)&B[(long long)(bn + nl) * ldb + k0 + k4];
                Bs[k4 + 0][nl] = vv.x;
                Bs[k4 + 1][nl] = vv.y;
                Bs[k4 + 2][nl] = vv.z;
                Bs[k4 + 3][nl] = vv.w;
            }
        } else {
            // B[K,N]: rows k (16), contiguous in n (128)
#pragma unroll
            for (int t = 0; t < 2; t++) {
                int fi = tid + t * 256;
                int kl = fi >> 5;
                int n4 = (fi & 31) << 2;
                float4 vv = *(const float4*)&B[(long long)(k0 + kl) * ldb + bn + n4];
                *(float4*)&Bs[kl][n4] = vv;
            }
        }
        __syncthreads();

#pragma unroll
        for (int kk = 0; kk < BK; kk++) {
            float ra[TM], rb[TN];
#pragma unroll
            for (int i = 0; i < TM; i += 4)
                *(float4*)&ra[i] = *(const float4*)&As[kk][ty * TM + i];
#pragma unroll
            for (int j = 0; j < TN; j += 4)
                *(float4*)&rb[j] = *(const float4*)&Bs[kk][tx * TN + j];
#pragma unroll
            for (int i = 0; i < TM; i++)
#pragma unroll
                for (int j = 0; j < TN; j++)
                    acc[i][j] = fmaf(ra[i], rb[j], acc[i][j]);
        }
        __syncthreads();
    }

    // ---- epilogue: alpha * acc + bias[m] ----
#pragma unroll
    for (int i = 0; i < TM; i++) {
        int m = bm + ty * TM + i;
        float bv = bias ? bias[m] : 0.f;
#pragma unroll
        for (int j = 0; j < TN; j += 4) {
            float4 o;
            o.x = alpha * acc[i][j + 0] + bv;
            o.y = alpha * acc[i][j + 1] + bv;
            o.z = alpha * acc[i][j + 2] + bv;
            o.w = alpha * acc[i][j + 3] + bv;
            *(float4*)&C[(long long)m * ldc + bn + tx * TN + j] = o;
        }
    }
}

// ---------------- row softmax over last dim (len HW = 2304 = 9*256) ----------
__global__ __launch_bounds__(256)
void softmax_kernel(float* __restrict__ S)
{
    const long long row = blockIdx.x;
    float* p = S + row * (long long)HW;
    const int tid = threadIdx.x;

    float vals[9];
    float mx = -1e30f;
#pragma unroll
    for (int i = 0; i < 9; i++) {
        vals[i] = p[tid + i * 256];
        mx = fmaxf(mx, vals[i]);
    }
    // block max
#pragma unroll
    for (int o = 16; o > 0; o >>= 1) mx = fmaxf(mx, __shfl_xor_sync(0xFFFFFFFFu, mx, o));
    __shared__ float redmax[8];
    __shared__ float redsum[8];
    if ((tid & 31) == 0) redmax[tid >> 5] = mx;
    __syncthreads();
    float m = redmax[0];
#pragma unroll
    for (int i = 1; i < 8; i++) m = fmaxf(m, redmax[i]);

    float s = 0.f;
#pragma unroll
    for (int i = 0; i < 9; i++) {
        vals[i] = __expf(vals[i] - m);
        s += vals[i];
    }
#pragma unroll
    for (int o = 16; o > 0; o >>= 1) s += __shfl_xor_sync(0xFFFFFFFFu, s, o);
    if ((tid & 31) == 0) redsum[tid >> 5] = s;
    __syncthreads();
    float tot = 0.f;
#pragma unroll
    for (int i = 0; i < 8; i++) tot += redsum[i];
    float inv = 1.f / tot;
#pragma unroll
    for (int i = 0; i < 9; i++) p[tid + i * 256] = vals[i] * inv;
}

// ---------------- launch -----------------------------------------------------
extern "C" void kernel_launch(void* const* d_in, const int* in_sizes, int n_in,
                              void* d_out, int out_size)
{
    const float* locx = (const float*)d_in[0];
    const float* glox = (const float*)d_in[1];
    const float* Wq   = (const float*)d_in[2];
    const float* bq   = (const float*)d_in[3];
    const float* Wk   = (const float*)d_in[4];
    const float* bk   = (const float*)d_in[5];
    const float* Wv   = (const float*)d_in[6];
    const float* bv   = (const float*)d_in[7];
    const float* Wo   = (const float*)d_in[8];
    const float* bo   = (const float*)d_in[9];
    float* out = (float*)d_out;

    float *q, *k, *v, *s, *ctx;
    cudaGetSymbolAddress((void**)&q,   g_q);
    cudaGetSymbolAddress((void**)&k,   g_k);
    cudaGetSymbolAddress((void**)&v,   g_v);
    cudaGetSymbolAddress((void**)&s,   g_s);
    cudaGetSymbolAddress((void**)&ctx, g_ctx);

    const long long sBC = (long long)HIDDEN * HW;       // per-batch q/k/v/ctx stride
    const long long sS  = (long long)HW * HW;           // per-batch scores stride
    const float SCALE = 0.044194173824159216f;          // 1/sqrt(512)

    dim3 blk(256);
    dim3 gProj(HW / BN, HIDDEN / BM, BATCH);            // (18, 4, 8)
    dim3 gScore(HW / BN, HW / BM, BATCH);               // (18, 18, 8)

    // Q = Wq * locx + bq ; K = Wk * glox + bk ; V = Wv * glox + bv
    gemm_kernel<false, false><<<gProj, blk>>>(Wq, locx, q, bq,
        HIDDEN, HW, HIDDEN, HIDDEN, HW, HW, 0, sBC, sBC, 1.f);
    gemm_kernel<false, false><<<gProj, blk>>>(Wk, glox, k, bk,
        HIDDEN, HW, HIDDEN, HIDDEN, HW, HW, 0, sBC, sBC, 1.f);
    gemm_kernel<false, false><<<gProj, blk>>>(Wv, glox, v, bv,
        HIDDEN, HW, HIDDEN, HIDDEN, HW, HW, 0, sBC, sBC, 1.f);

    // S[n][m] = SCALE * sum_c q[c][n] * k[c][m]   (TN gemm)
    gemm_kernel<true, false><<<gScore, blk>>>(q, k, s, nullptr,
        HW, HW, HIDDEN, HW, HW, HW, sBC, sBC, sS, SCALE);

    // row softmax over m
    softmax_kernel<<<BATCH * HW, 256>>>(s);

    // ctx[c][n] = sum_m v[c][m] * P[n][m]   (NT gemm)
    gemm_kernel<false, true><<<gProj, blk>>>(v, s, ctx, nullptr,
        HIDDEN, HW, HW, HW, HW, HW, sBC, sS, sBC, 1.f);

    // out = Wo * ctx + bo
    gemm_kernel<false, false><<<gProj, blk>>>(Wo, ctx, out, bo,
        HIDDEN, HW, HIDDEN, HIDDEN, HW, HW, 0, sBC, sBC, 1.f);
}

// round 2
// speedup vs baseline: 2.0130x; 2.0130x over previous
#include <cuda_runtime.h>
#include <math.h>
#include <stdint.h>

#define HIDDEN 512
#define BATCH  8
#define HW     2304   // 48*48

// ---------------- scratch (static device globals; no allocs allowed) ----------
static __device__ float g_q  [(size_t)BATCH * HIDDEN * HW];
static __device__ float g_k  [(size_t)BATCH * HIDDEN * HW];
static __device__ float g_v  [(size_t)BATCH * HIDDEN * HW];
static __device__ float g_ctx[(size_t)BATCH * HIDDEN * HW];
static __device__ float g_s  [(size_t)BATCH * HW * HW];

// ---------------- tf32 helpers ------------------------------------------------
__device__ __forceinline__ unsigned f2tf32(float f) {
    unsigned u;
    asm("cvt.rna.tf32.f32 %0, %1;" : "=r"(u) : "f"(f));
    return u;
}

__device__ __forceinline__ void mma_tf32(float& c0, float& c1, float& c2, float& c3,
                                         unsigned a0, unsigned a1, unsigned a2, unsigned a3,
                                         unsigned b0, unsigned b1)
{
    asm volatile(
        "mma.sync.aligned.m16n8k8.row.col.f32.tf32.tf32.f32 "
        "{%0,%1,%2,%3}, {%4,%5,%6,%7}, {%8,%9}, {%0,%1,%2,%3};"
        : "+f"(c0), "+f"(c1), "+f"(c2), "+f"(c3)
        : "r"(a0), "r"(a1), "r"(a2), "r"(a3), "r"(b0), "r"(b1));
}

// ---------------- batched tiled tf32 tensor-core GEMM -------------------------
// C[m][n] = alpha * sum_k opA(m,k) * opB(k,n) + bias[m]
//   TA=0: A is [M,K] row-major      TA=1: A is [K,M] (m contiguous)
//   TB=0: B is [K,N] (n contiguous) TB=1: B is [N,K] (k contiguous)
// M,N divisible by 128; K divisible by 16 (true for every call here).
constexpr int BM = 128, BN = 128, BK = 16, PAD = 8;
constexpr int LDA_S = BM + PAD;   // 136: 136 mod 32 = 8 -> conflict-free frags
constexpr int LDB_S = BN + PAD;

template<bool TA, bool TB>
__global__ __launch_bounds__(256)
void gemm_tf32(const float* __restrict__ A, const float* __restrict__ B,
               float* __restrict__ C, const float* __restrict__ bias,
               int M, int N, int K, int lda, int ldb, int ldc,
               long long sA, long long sB, long long sC, float alpha)
{
    __shared__ unsigned As[2][BK][LDA_S];
    __shared__ unsigned Bs[2][BK][LDB_S];

    const int bz = blockIdx.z;
    A += (long long)bz * sA;
    B += (long long)bz * sB;
    C += (long long)bz * sC;

    const int bm = blockIdx.y * BM;
    const int bn = blockIdx.x * BN;
    const int tid  = threadIdx.x;          // 256 threads
    const int warp = tid >> 5;
    const int lane = tid & 31;
    const int lr = lane >> 2;              // 0..7
    const int lc = lane & 3;               // 0..3
    const int warp_m = (warp & 1) * 64;    // 2 warps in m
    const int warp_n = (warp >> 1) * 32;   // 4 warps in n

    float acc[4][4][4];                    // [m-tile][n-tile][reg]
#pragma unroll
    for (int i = 0; i < 4; i++)
#pragma unroll
        for (int j = 0; j < 4; j++)
#pragma unroll
            for (int r = 0; r < 4; r++) acc[i][j][r] = 0.f;

    float4 ra[2], rb[2];                   // staging registers

    // ---- global load into staging regs for k-chunk k0 ----
    auto LDG = [&](int k0) {
#pragma unroll
        for (int t = 0; t < 2; t++) {
            int fi = tid + t * 256;        // 0..511 float4 ids
            if (TA) {                      // A[K,M]: rows k, m contiguous
                int kl = fi >> 5;          // 0..15
                int m4 = (fi & 31) << 2;   // 0..124
                ra[t] = *(const float4*)&A[(long long)(kl) * lda + bm + m4];
            } else {                       // A[M,K]: k contiguous
                int ksel = fi >> 7;        // 0..3 -> k4 = ksel*4
                int ml = fi & 127;
                ra[t] = *(const float4*)&A[(long long)(bm + ml) * lda + (ksel << 2)];
            }
            if (TB) {                      // B[N,K]: k contiguous
                int ksel = fi >> 7;
                int nl = fi & 127;
                rb[t] = *(const float4*)&B[(long long)(bn + nl) * ldb + (ksel << 2)];
            } else {                       // B[K,N]: n contiguous
                int kl = fi >> 5;
                int n4 = (fi & 31) << 2;
                rb[t] = *(const float4*)&B[(long long)(kl) * ldb + bn + n4];
            }
        }
    };

    auto STS = [&](int buf) {
#pragma unroll
        for (int t = 0; t < 2; t++) {
            int fi = tid + t * 256;
            if (TA) {
                int kl = fi >> 5;
                int m4 = (fi & 31) << 2;
                uint4 u = { f2tf32(ra[t].x), f2tf32(ra[t].y), f2tf32(ra[t].z), f2tf32(ra[t].w) };
                *(uint4*)&As[buf][kl][m4] = u;
            } else {
                int ksel = fi >> 7;
                int ml = fi & 127;
                int k4 = ksel << 2;
                As[buf][k4 + 0][ml] = f2tf32(ra[t].x);
                As[buf][k4 + 1][ml] = f2tf32(ra[t].y);
                As[buf][k4 + 2][ml] = f2tf32(ra[t].z);
                As[buf][k4 + 3][ml] = f2tf32(ra[t].w);
            }
            if (TB) {
                int ksel = fi >> 7;
                int nl = fi & 127;
                int k4 = ksel << 2;
                Bs[buf][k4 + 0][nl] = f2tf32(rb[t].x);
                Bs[buf][k4 + 1][nl] = f2tf32(rb[t].y);
                Bs[buf][k4 + 2][nl] = f2tf32(rb[t].z);
                Bs[buf][k4 + 3][nl] = f2tf32(rb[t].w);
            } else {
                int kl = fi >> 5;
                int n4 = (fi & 31) << 2;
                uint4 u = { f2tf32(rb[t].x), f2tf32(rb[t].y), f2tf32(rb[t].z), f2tf32(rb[t].w) };
                *(uint4*)&Bs[buf][kl][n4] = u;
            }
        }
    };

    const int nT = K / BK;
    LDG(0);
    STS(0);
    __syncthreads();

    for (int t = 0; t < nT; t++) {
        const int cur = t & 1;
        if (t + 1 < nT) {
            // advance base pointers by one k-chunk, reload staging regs
            A += TA ? (long long)BK * lda : BK;
            B += TB ? BK : (long long)BK * ldb;
            LDG(0);
        }
        // ---- compute two k=8 steps from current buffer ----
#pragma unroll
        for (int ks = 0; ks < 2; ks++) {
            const int kk = ks * 8;
            unsigned af[4][4], bf[4][2];
#pragma unroll
            for (int ti = 0; ti < 4; ti++) {
                int m0 = warp_m + ti * 16;
                af[ti][0] = As[cur][kk + lc    ][m0 + lr    ];
                af[ti][1] = As[cur][kk + lc    ][m0 + lr + 8];
                af[ti][2] = As[cur][kk + lc + 4][m0 + lr    ];
                af[ti][3] = As[cur][kk + lc + 4][m0 + lr + 8];
            }
#pragma unroll
            for (int tj = 0; tj < 4; tj++) {
                int n0 = warp_n + tj * 8;
                bf[tj][0] = Bs[cur][kk + lc    ][n0 + lr];
                bf[tj][1] = Bs[cur][kk + lc + 4][n0 + lr];
            }
#pragma unroll
            for (int ti = 0; ti < 4; ti++)
#pragma unroll
                for (int tj = 0; tj < 4; tj++)
                    mma_tf32(acc[ti][tj][0], acc[ti][tj][1], acc[ti][tj][2], acc[ti][tj][3],
                             af[ti][0], af[ti][1], af[ti][2], af[ti][3],
                             bf[tj][0], bf[tj][1]);
        }
        if (t + 1 < nT) {
            STS(cur ^ 1);
            __syncthreads();
        }
    }

    // ---- epilogue: alpha * acc + bias[m] ----
    // c0: (row = lr, col = 2*lc), c1: col+1, c2: row+8, c3: row+8,col+1
#pragma unroll
    for (int ti = 0; ti < 4; ti++) {
        int r0 = bm + warp_m + ti * 16 + lr;
        int r1 = r0 + 8;
        float bv0 = bias ? bias[r0] : 0.f;
        float bv1 = bias ? bias[r1] : 0.f;
#pragma unroll
        for (int tj = 0; tj < 4; tj++) {
            int n0 = bn + warp_n + tj * 8 + 2 * lc;
            float2 o0 = { alpha * acc[ti][tj][0] + bv0, alpha * acc[ti][tj][1] + bv0 };
            float2 o1 = { alpha * acc[ti][tj][2] + bv1, alpha * acc[ti][tj][3] + bv1 };
            *(float2*)&C[(long long)r0 * ldc + n0] = o0;
            *(float2*)&C[(long long)r1 * ldc + n0] = o1;
        }
    }
}

// ---------------- row softmax over last dim (len HW = 2304 = 9*256) ----------
__global__ __launch_bounds__(256)
void softmax_kernel(float* __restrict__ S)
{
    const long long row = blockIdx.x;
    float* p = S + row * (long long)HW;
    const int tid = threadIdx.x;

    float vals[9];
    float mx = -1e30f;
#pragma unroll
    for (int i = 0; i < 9; i++) {
        vals[i] = p[tid + i * 256];
        mx = fmaxf(mx, vals[i]);
    }
#pragma unroll
    for (int o = 16; o > 0; o >>= 1) mx = fmaxf(mx, __shfl_xor_sync(0xFFFFFFFFu, mx, o));
    __shared__ float redmax[8];
    __shared__ float redsum[8];
    if ((tid & 31) == 0) redmax[tid >> 5] = mx;
    __syncthreads();
    float m = redmax[0];
#pragma unroll
    for (int i = 1; i < 8; i++) m = fmaxf(m, redmax[i]);

    float s = 0.f;
#pragma unroll
    for (int i = 0; i < 9; i++) {
        vals[i] = __expf(vals[i] - m);
        s += vals[i];
    }
#pragma unroll
    for (int o = 16; o > 0; o >>= 1) s += __shfl_xor_sync(0xFFFFFFFFu, s, o);
    if ((tid & 31) == 0) redsum[tid >> 5] = s;
    __syncthreads();
    float tot = 0.f;
#pragma unroll
    for (int i = 0; i < 8; i++) tot += redsum[i];
    float inv = 1.f / tot;
#pragma unroll
    for (int i = 0; i < 9; i++) p[tid + i * 256] = vals[i] * inv;
}

// ---------------- launch -----------------------------------------------------
extern "C" void kernel_launch(void* const* d_in, const int* in_sizes, int n_in,
                              void* d_out, int out_size)
{
    const float* locx = (const float*)d_in[0];
    const float* glox = (const float*)d_in[1];
    const float* Wq   = (const float*)d_in[2];
    const float* bq   = (const float*)d_in[3];
    const float* Wk   = (const float*)d_in[4];
    const float* bk   = (const float*)d_in[5];
    const float* Wv   = (const float*)d_in[6];
    const float* bv   = (const float*)d_in[7];
    const float* Wo   = (const float*)d_in[8];
    const float* bo   = (const float*)d_in[9];
    float* out = (float*)d_out;

    float *q, *k, *v, *s, *ctx;
    cudaGetSymbolAddress((void**)&q,   g_q);
    cudaGetSymbolAddress((void**)&k,   g_k);
    cudaGetSymbolAddress((void**)&v,   g_v);
    cudaGetSymbolAddress((void**)&s,   g_s);
    cudaGetSymbolAddress((void**)&ctx, g_ctx);

    const long long sBC = (long long)HIDDEN * HW;       // per-batch q/k/v/ctx stride
    const long long sS  = (long long)HW * HW;           // per-batch scores stride
    const float SCALE = 0.044194173824159216f;          // 1/sqrt(512)

    dim3 blk(256);
    dim3 gProj(HW / BN, HIDDEN / BM, BATCH);            // (18, 4, 8)
    dim3 gScore(HW / BN, HW / BM, BATCH);               // (18, 18, 8)

    // Q = Wq * locx + bq ; K = Wk * glox + bk ; V = Wv * glox + bv
    gemm_tf32<false, false><<<gProj, blk>>>(Wq, locx, q, bq,
        HIDDEN, HW, HIDDEN, HIDDEN, HW, HW, 0, sBC, sBC, 1.f);
    gemm_tf32<false, false><<<gProj, blk>>>(Wk, glox, k, bk,
        HIDDEN, HW, HIDDEN, HIDDEN, HW, HW, 0, sBC, sBC, 1.f);
    gemm_tf32<false, false><<<gProj, blk>>>(Wv, glox, v, bv,
        HIDDEN, HW, HIDDEN, HIDDEN, HW, HW, 0, sBC, sBC, 1.f);

    // S[n][m] = SCALE * sum_c q[c][n] * k[c][m]   (TN gemm)
    gemm_tf32<true, false><<<gScore, blk>>>(q, k, s, nullptr,
        HW, HW, HIDDEN, HW, HW, HW, sBC, sBC, sS, SCALE);

    // row softmax over m
    softmax_kernel<<<BATCH * HW, 256>>>(s);

    // ctx[c][n] = sum_m v[c][m] * P[n][m]   (NT gemm)
    gemm_tf32<false, true><<<gProj, blk>>>(v, s, ctx, nullptr,
        HIDDEN, HW, HW, HW, HW, HW, sBC, sS, sBC, 1.f);

    // out = Wo * ctx + bo
    gemm_tf32<false, false><<<gProj, blk>>>(Wo, ctx, out, bo,
        HIDDEN, HW, HIDDEN, HIDDEN, HW, HW, 0, sBC, sBC, 1.f);
}